// round 12
// baseline (speedup 1.0000x reference)
#include <cuda_runtime.h>
#include <cuda_bf16.h>
#include <math.h>
#include <stdint.h>

// Problem constants
#define T_TOKENS 16384
#define DDIM     1024
#define NEXP     8

// GEMM tiling
#define BM 128
#define BN 64
#define BK 64                      // bf16 elems per k-slab = 128B rows
#define LDR 72                     // 64 data + 8 pad bf16 = 144B stride (conflict-free)
#define NSLAB (DDIM / BK)          // 16
#define MAXTILES 264               // sum ceil(cnt_e/BM) <= 32768/128 + 8

// stage layout (bytes): Ah | Al | Bh | Bl
#define A_BYTES (BM * LDR * 2)     // 18432
#define B_BYTES (BN * LDR * 2)     // 9216
#define OFF_AH 0
#define OFF_AL A_BYTES
#define OFF_BH (2 * A_BYTES)
#define OFF_BL (2 * A_BYTES + B_BYTES)
#define STAGE_BYTES (2 * A_BYTES + 2 * B_BYTES)    // 55296
#define SMEM_DYN (2 * STAGE_BYTES)                 // 110592 -> 2 CTAs/SM

// ---------------- scratch (static device globals; no allocation) ------------
__device__ int    g_count[NEXP];
__device__ int    g_base[NEXP];
__device__ int    g_tok[NEXP][T_TOKENS];
__device__ int4   g_assign[T_TOKENS];
__device__ float2 g_tw[T_TOKENS];
__device__ int    g_ntiles;
__device__ int    g_te[MAXTILES];
__device__ int    g_trow[MAXTILES];

__device__ __nv_bfloat16 g_xh[T_TOKENS * DDIM];
__device__ __nv_bfloat16 g_xl[T_TOKENS * DDIM];
__device__ __nv_bfloat16 g_w1h[NEXP * DDIM * DDIM];
__device__ __nv_bfloat16 g_w1l[NEXP * DDIM * DDIM];
__device__ __nv_bfloat16 g_w2h[NEXP * DDIM * DDIM];
__device__ __nv_bfloat16 g_w2l[NEXP * DDIM * DDIM];
__device__ __nv_bfloat16 g_Hh[2 * T_TOKENS * DDIM];
__device__ __nv_bfloat16 g_Hl[2 * T_TOKENS * DDIM];
__device__ float         g_Y[2 * T_TOKENS * DDIM];

// ---------------- helpers ----------------------------------------------------
static __device__ __forceinline__ uint32_t smem_u32(const void* p) {
    uint32_t a;
    asm("{ .reg .u64 t; cvta.to.shared.u64 t, %1; cvt.u32.u64 %0, t; }"
        : "=r"(a) : "l"(p));
    return a;
}
static __device__ __forceinline__ void cp16(uint32_t dst, const void* src) {
    asm volatile("cp.async.cg.shared.global [%0], [%1], 16;" :: "r"(dst), "l"(src));
}
static __device__ __forceinline__ void cp_commit() {
    asm volatile("cp.async.commit_group;" ::: "memory");
}
static __device__ __forceinline__ void cp_wait1() {
    asm volatile("cp.async.wait_group 1;" ::: "memory");
}

static __device__ __forceinline__ void ldsm4(uint32_t* r, const __nv_bfloat16* p) {
    uint32_t a = (uint32_t)__cvta_generic_to_shared(p);
    asm volatile("ldmatrix.sync.aligned.m8n8.x4.shared.b16 {%0,%1,%2,%3}, [%4];"
                 : "=r"(r[0]), "=r"(r[1]), "=r"(r[2]), "=r"(r[3])
                 : "r"(a));
}
static __device__ __forceinline__ void mma16816(float* c, const uint32_t* a, const uint32_t* b) {
    asm volatile("mma.sync.aligned.m16n8k16.row.col.f32.bf16.bf16.f32 "
                 "{%0,%1,%2,%3},{%4,%5,%6,%7},{%8,%9},{%0,%1,%2,%3};"
                 : "+f"(c[0]), "+f"(c[1]), "+f"(c[2]), "+f"(c[3])
                 : "r"(a[0]), "r"(a[1]), "r"(a[2]), "r"(a[3]),
                   "r"(b[0]), "r"(b[1]));
}

// ---------------- init ------------------------------------------------------
__global__ void init_counts_kernel() {
    if (threadIdx.x < NEXP) {
        g_count[threadIdx.x] = 0;
    }
}

// ---------------- fp32 -> bf16 hi/lo split (weights) --------------------------
__global__ void conv_split_kernel(const float* __restrict__ src, int which, int n4) {
    __nv_bfloat16* hi;
    __nv_bfloat16* lo;
    if (which == 1) { hi = g_w1h; lo = g_w1l; }
    else            { hi = g_w2h; lo = g_w2l; }

    int idx = blockIdx.x * blockDim.x + threadIdx.x;
    const int stride = gridDim.x * blockDim.x;
    for (; idx < n4; idx += stride) {
        float4 v = ((const float4*)src)[idx];
        __nv_bfloat16 h0 = __float2bfloat16_rn(v.x);
        __nv_bfloat16 h1 = __float2bfloat16_rn(v.y);
        __nv_bfloat16 h2 = __float2bfloat16_rn(v.z);
        __nv_bfloat16 h3 = __float2bfloat16_rn(v.w);
        __nv_bfloat16 l0 = __float2bfloat16_rn(v.x - __bfloat162float(h0));
        __nv_bfloat16 l1 = __float2bfloat16_rn(v.y - __bfloat162float(h1));
        __nv_bfloat16 l2 = __float2bfloat16_rn(v.z - __bfloat162float(h2));
        __nv_bfloat16 l3 = __float2bfloat16_rn(v.w - __bfloat162float(h3));
        __nv_bfloat162 hv0 = __halves2bfloat162(h0, h1);
        __nv_bfloat162 hv1 = __halves2bfloat162(h2, h3);
        __nv_bfloat162 lv0 = __halves2bfloat162(l0, l1);
        __nv_bfloat162 lv1 = __halves2bfloat162(l2, l3);
        uint2 hv;
        hv.x = *reinterpret_cast<uint32_t*>(&hv0);
        hv.y = *reinterpret_cast<uint32_t*>(&hv1);
        uint2 lv;
        lv.x = *reinterpret_cast<uint32_t*>(&lv0);
        lv.y = *reinterpret_cast<uint32_t*>(&lv1);
        ((uint2*)hi)[idx] = hv;
        ((uint2*)lo)[idx] = lv;
    }
}

// ---------------- router (also emits x hi/lo split) ---------------------------
__global__ void router_kernel(const float* __restrict__ x,
                              const float* __restrict__ Wr) {
    __shared__ __align__(16) float sWr[NEXP * DDIM];
    for (int i = threadIdx.x; i < NEXP * DDIM; i += blockDim.x) {
        sWr[i] = Wr[i];
    }
    __syncthreads();

    const int warp = threadIdx.x >> 5;
    const int lane = threadIdx.x & 31;
    const int t = blockIdx.x * 8 + warp;

    const float4* xr = (const float4*)(x + (size_t)t * DDIM);
    const float4* wr = (const float4*)sWr;
    uint2* xh = (uint2*)(g_xh + (size_t)t * DDIM);
    uint2* xl = (uint2*)(g_xl + (size_t)t * DDIM);

    float acc[NEXP];
#pragma unroll
    for (int e = 0; e < NEXP; e++) {
        acc[e] = 0.f;
    }

    for (int i = lane; i < DDIM / 4; i += 32) {
        float4 xv = xr[i];
        // split x into bf16 hi/lo and store
        {
            __nv_bfloat16 h0 = __float2bfloat16_rn(xv.x);
            __nv_bfloat16 h1 = __float2bfloat16_rn(xv.y);
            __nv_bfloat16 h2 = __float2bfloat16_rn(xv.z);
            __nv_bfloat16 h3 = __float2bfloat16_rn(xv.w);
            __nv_bfloat16 l0 = __float2bfloat16_rn(xv.x - __bfloat162float(h0));
            __nv_bfloat16 l1 = __float2bfloat16_rn(xv.y - __bfloat162float(h1));
            __nv_bfloat16 l2 = __float2bfloat16_rn(xv.z - __bfloat162float(h2));
            __nv_bfloat16 l3 = __float2bfloat16_rn(xv.w - __bfloat162float(h3));
            __nv_bfloat162 hv0 = __halves2bfloat162(h0, h1);
            __nv_bfloat162 hv1 = __halves2bfloat162(h2, h3);
            __nv_bfloat162 lv0 = __halves2bfloat162(l0, l1);
            __nv_bfloat162 lv1 = __halves2bfloat162(l2, l3);
            uint2 hv;
            hv.x = *reinterpret_cast<uint32_t*>(&hv0);
            hv.y = *reinterpret_cast<uint32_t*>(&hv1);
            uint2 lv;
            lv.x = *reinterpret_cast<uint32_t*>(&lv0);
            lv.y = *reinterpret_cast<uint32_t*>(&lv1);
            xh[i] = hv;
            xl[i] = lv;
        }
#pragma unroll
        for (int e = 0; e < NEXP; e++) {
            float4 wv = wr[e * (DDIM / 4) + i];
            acc[e] += xv.x * wv.x + xv.y * wv.y + xv.z * wv.z + xv.w * wv.w;
        }
    }
#pragma unroll
    for (int e = 0; e < NEXP; e++) {
#pragma unroll
        for (int off = 16; off; off >>= 1) {
            acc[e] += __shfl_xor_sync(0xffffffffu, acc[e], off);
        }
    }

    if (lane == 0) {
        int i1 = 0;
        float m1 = acc[0];
#pragma unroll
        for (int e = 1; e < NEXP; e++) {
            if (acc[e] > m1) { m1 = acc[e]; i1 = e; }
        }
        int i2 = -1;
        float m2 = -INFINITY;
#pragma unroll
        for (int e = 0; e < NEXP; e++) {
            if (e != i1 && acc[e] > m2) { m2 = acc[e]; i2 = e; }
        }

        float w1 = 1.0f / (1.0f + expf(m2 - m1));
        float w2 = 1.0f - w1;

        int p1 = atomicAdd(&g_count[i1], 1);
        g_tok[i1][p1] = t;
        int p2 = atomicAdd(&g_count[i2], 1);
        g_tok[i2][p2] = t;
        g_assign[t] = make_int4(i1, p1, i2, p2);
        g_tw[t] = make_float2(w1, w2);
    }
}

// ---------------- prefix + tile table -----------------------------------------
__global__ void prefix_kernel() {
    if (threadIdx.x == 0) {
        int s = 0;
        int nt = 0;
#pragma unroll
        for (int e = 0; e < NEXP; e++) {
            g_base[e] = s;
            const int c = g_count[e];
            const int tiles = (c + BM - 1) / BM;
            for (int i = 0; i < tiles; i++) {
                g_te[nt] = e;
                g_trow[nt] = i * BM;
                nt++;
            }
            s += c;
        }
        g_ntiles = nt;
    }
}

// ---------------- gemm building blocks ---------------------------------------
static __device__ __forceinline__ void compute_slab(
    const __nv_bfloat16* sAh, const __nv_bfloat16* sAl,
    const __nv_bfloat16* sBh, const __nv_bfloat16* sBl,
    int aLd, int bLd, float acc[2][4][4]) {
#pragma unroll
    for (int kk = 0; kk < BK; kk += 16) {
        uint32_t ah0[4];
        uint32_t ah1[4];
        uint32_t al0[4];
        uint32_t al1[4];
        uint32_t bh0[4];
        uint32_t bh1[4];
        uint32_t bl0[4];
        uint32_t bl1[4];
        ldsm4(ah0, sAh + aLd + kk);
        ldsm4(ah1, sAh + aLd + 16 * LDR + kk);
        ldsm4(al0, sAl + aLd + kk);
        ldsm4(al1, sAl + aLd + 16 * LDR + kk);
        ldsm4(bh0, sBh + bLd + kk);
        ldsm4(bh1, sBh + bLd + 16 * LDR + kk);
        ldsm4(bl0, sBl + bLd + kk);
        ldsm4(bl1, sBl + bLd + 16 * LDR + kk);

        mma16816(acc[0][0], ah0, &bh0[0]);
        mma16816(acc[0][1], ah0, &bh0[2]);
        mma16816(acc[0][2], ah0, &bh1[0]);
        mma16816(acc[0][3], ah0, &bh1[2]);
        mma16816(acc[1][0], ah1, &bh0[0]);
        mma16816(acc[1][1], ah1, &bh0[2]);
        mma16816(acc[1][2], ah1, &bh1[0]);
        mma16816(acc[1][3], ah1, &bh1[2]);

        mma16816(acc[0][0], ah0, &bl0[0]);
        mma16816(acc[0][1], ah0, &bl0[2]);
        mma16816(acc[0][2], ah0, &bl1[0]);
        mma16816(acc[0][3], ah0, &bl1[2]);
        mma16816(acc[1][0], ah1, &bl0[0]);
        mma16816(acc[1][1], ah1, &bl0[2]);
        mma16816(acc[1][2], ah1, &bl1[0]);
        mma16816(acc[1][3], ah1, &bl1[2]);

        mma16816(acc[0][0], al0, &bh0[0]);
        mma16816(acc[0][1], al0, &bh0[2]);
        mma16816(acc[0][2], al0, &bh1[0]);
        mma16816(acc[0][3], al0, &bh1[2]);
        mma16816(acc[1][0], al1, &bh0[0]);
        mma16816(acc[1][1], al1, &bh0[2]);
        mma16816(acc[1][2], al1, &bh1[0]);
        mma16816(acc[1][3], al1, &bh1[2]);
    }
}

// ============================================================================
// bf16x3 tensor-core grouped GEMM. BK=64 slabs, 2-stage cp.async double buffer,
// compacted tile grid (no dead CTAs).
// EPI 0: A = gathered x rows (hi/lo), B = W1[e], gelu(c+b1) -> g_Hh/g_Hl
// EPI 1: A = packed H rows,           B = W2[e], raw c      -> g_Y
// ============================================================================
template <int EPI>
__global__ void __launch_bounds__(256, 2)
gemm_mma_kernel(const float* __restrict__ bias) {
    const int tix = blockIdx.y;
    if (tix >= g_ntiles) { return; }
    const int e    = g_te[tix];
    const int row0 = g_trow[tix];
    const int cnt  = g_count[e];
    const int base = g_base[e];
    const int col0 = blockIdx.x * BN;

    extern __shared__ __align__(128) char dsmem[];
    const uint32_t sb = smem_u32(dsmem);

    const int tid  = threadIdx.x;
    const int lane = tid & 31;
    const int wid  = tid >> 5;

    // ---- cp.async assignment: cq = 16B chunk (0..7), rowq = row (0..31) -------
    const int cq   = tid & 7;
    const int rowq = tid >> 3;

    const __nv_bfloat16* Ah;
    const __nv_bfloat16* Al;
    const __nv_bfloat16* Bh;
    const __nv_bfloat16* Bl;
    size_t aIdx[4];
    size_t bIdx[2];
    if (EPI == 0) {
        Ah = g_xh;
        Al = g_xl;
        Bh = g_w1h;
        Bl = g_w1l;
#pragma unroll
        for (int j = 0; j < 4; j++) {
            int r = row0 + rowq + 32 * j;
            if (r >= cnt) { r = cnt - 1; }
            aIdx[j] = (size_t)g_tok[e][r] * DDIM + cq * 8;
        }
    } else {
        Ah = g_Hh;
        Al = g_Hl;
        Bh = g_w2h;
        Bl = g_w2l;
#pragma unroll
        for (int j = 0; j < 4; j++) {
            int r = row0 + rowq + 32 * j;
            if (r >= cnt) { r = cnt - 1; }
            aIdx[j] = (size_t)(base + r) * DDIM + cq * 8;
        }
    }
#pragma unroll
    for (int j = 0; j < 2; j++) {
        bIdx[j] = ((size_t)e * DDIM + col0 + rowq + 32 * j) * DDIM + cq * 8;
    }

    uint32_t oA[4];
#pragma unroll
    for (int j = 0; j < 4; j++) {
        oA[j] = (uint32_t)(rowq + 32 * j) * 144u + (uint32_t)cq * 16u;
    }

    const uint32_t st0 = sb;
    const uint32_t st1 = sb + STAGE_BYTES;
    const __nv_bfloat16* s0Ah = (const __nv_bfloat16*)(dsmem + OFF_AH);
    const __nv_bfloat16* s0Al = (const __nv_bfloat16*)(dsmem + OFF_AL);
    const __nv_bfloat16* s0Bh = (const __nv_bfloat16*)(dsmem + OFF_BH);
    const __nv_bfloat16* s0Bl = (const __nv_bfloat16*)(dsmem + OFF_BL);
    const __nv_bfloat16* s1Ah = (const __nv_bfloat16*)(dsmem + STAGE_BYTES + OFF_AH);
    const __nv_bfloat16* s1Al = (const __nv_bfloat16*)(dsmem + STAGE_BYTES + OFF_AL);
    const __nv_bfloat16* s1Bh = (const __nv_bfloat16*)(dsmem + STAGE_BYTES + OFF_BH);
    const __nv_bfloat16* s1Bl = (const __nv_bfloat16*)(dsmem + STAGE_BYTES + OFF_BL);

    // ---- mma fragment smem offsets (bf16 elems) -------------------------------
    const int wm = (wid & 3) * 32;
    const int wn = (wid >> 2) * 32;
    const int aLd = (wm + (lane & 15)) * LDR + ((lane >> 4) << 3);
    const int bLd = (wn + ((lane >> 4) << 3) + (lane & 7)) * LDR + (lane & 8);

    float acc[2][4][4];
#pragma unroll
    for (int i = 0; i < 2; i++) {
#pragma unroll
        for (int j = 0; j < 4; j++) {
#pragma unroll
            for (int q = 0; q < 4; q++) {
                acc[i][j][q] = 0.f;
            }
        }
    }

    // ---- refill macro-ish lambda -------------------------------------------------
    auto refill = [&](uint32_t st, int k0) {
#pragma unroll
        for (int j = 0; j < 4; j++) {
            cp16(st + OFF_AH + oA[j], Ah + aIdx[j] + k0);
            cp16(st + OFF_AL + oA[j], Al + aIdx[j] + k0);
        }
#pragma unroll
        for (int j = 0; j < 2; j++) {
            cp16(st + OFF_BH + oA[j], Bh + bIdx[j] + k0);
            cp16(st + OFF_BL + oA[j], Bl + bIdx[j] + k0);
        }
    };

    // ---- prologue: slabs 0,1 -> stages 0,1 --------------------------------------
    refill(st0, 0);
    cp_commit();
    refill(st1, BK);
    cp_commit();

    // ---- mainloop: slab j -> stage j&1; after compute, refill same stage ---------
    for (int j = 0; j < NSLAB; j += 2) {
        cp_wait1();
        __syncthreads();
        compute_slab(s0Ah, s0Al, s0Bh, s0Bl, aLd, bLd, acc);
        __syncthreads();
        if (j + 2 < NSLAB) {
            refill(st0, (j + 2) * BK);
        }
        cp_commit();

        cp_wait1();
        __syncthreads();
        compute_slab(s1Ah, s1Al, s1Bh, s1Bl, aLd, bLd, acc);
        __syncthreads();
        if (j + 3 < NSLAB) {
            refill(st1, (j + 3) * BK);
        }
        cp_commit();
    }

    // ---- epilogue ----------------------------------------------------------------
    const int r0l = lane >> 2;
    const int c0l = (lane & 3) * 2;
#pragma unroll
    for (int mt = 0; mt < 2; mt++) {
#pragma unroll
        for (int nt = 0; nt < 4; nt++) {
            const int fc = col0 + wn + nt * 8 + c0l;
#pragma unroll
            for (int half = 0; half < 2; half++) {
                const int r = row0 + wm + mt * 16 + r0l + half * 8;
                if (r < cnt) {
                    float v0 = acc[mt][nt][half * 2 + 0];
                    float v1 = acc[mt][nt][half * 2 + 1];
                    if (EPI == 0) {
                        float2 bb = *(const float2*)(bias + (size_t)e * DDIM + fc);
                        v0 += bb.x;
                        v1 += bb.y;
                        v0 = 0.5f * v0 * (1.0f + erff(v0 * 0.70710678118654752f));
                        v1 = 0.5f * v1 * (1.0f + erff(v1 * 0.70710678118654752f));
                        __nv_bfloat16 h0 = __float2bfloat16_rn(v0);
                        __nv_bfloat16 h1 = __float2bfloat16_rn(v1);
                        __nv_bfloat16 l0 = __float2bfloat16_rn(v0 - __bfloat162float(h0));
                        __nv_bfloat16 l1 = __float2bfloat16_rn(v1 - __bfloat162float(h1));
                        *(__nv_bfloat162*)(g_Hh + (size_t)(base + r) * DDIM + fc) =
                            __halves2bfloat162(h0, h1);
                        *(__nv_bfloat162*)(g_Hl + (size_t)(base + r) * DDIM + fc) =
                            __halves2bfloat162(l0, l1);
                    } else {
                        *(float2*)(g_Y + (size_t)(base + r) * DDIM + fc) = make_float2(v0, v1);
                    }
                }
            }
        }
    }
}

// ---------------- combine: out[t] = w1*(y1+b2[e1]) + w2*(y2+b2[e2]) ----------
__global__ void combine_kernel(const float* __restrict__ b2,
                               float* __restrict__ out) {
    const int idx = blockIdx.x * blockDim.x + threadIdx.x;
    const int t = idx >> 8;        // DDIM/4 = 256 float4 per token
    const int c4 = idx & 255;
    int4 a = g_assign[t];
    float2 w = g_tw[t];
    const int s1 = g_base[a.x] + a.y;
    const int s2 = g_base[a.z] + a.w;
    float4 y1 = *(const float4*)(g_Y + (size_t)s1 * DDIM + c4 * 4);
    float4 y2 = *(const float4*)(g_Y + (size_t)s2 * DDIM + c4 * 4);
    float4 v1 = *(const float4*)(b2 + (size_t)a.x * DDIM + c4 * 4);
    float4 v2 = *(const float4*)(b2 + (size_t)a.z * DDIM + c4 * 4);
    float4 o;
    o.x = w.x * (y1.x + v1.x) + w.y * (y2.x + v2.x);
    o.y = w.x * (y1.y + v1.y) + w.y * (y2.y + v2.y);
    o.z = w.x * (y1.z + v1.z) + w.y * (y2.z + v2.z);
    o.w = w.x * (y1.w + v1.w) + w.y * (y2.w + v2.w);
    ((float4*)out)[idx] = o;
}

// ---------------- launch -----------------------------------------------------
extern "C" void kernel_launch(void* const* d_in, const int* in_sizes, int n_in,
                              void* d_out, int out_size) {
    const float* x  = (const float*)d_in[0];
    const float* Wr = (const float*)d_in[1];
    const float* W1 = (const float*)d_in[2];
    const float* b1 = (const float*)d_in[3];
    const float* W2 = (const float*)d_in[4];
    const float* b2 = (const float*)d_in[5];
    float* out = (float*)d_out;

    cudaFuncSetAttribute(gemm_mma_kernel<0>,
                         cudaFuncAttributeMaxDynamicSharedMemorySize, SMEM_DYN);
    cudaFuncSetAttribute(gemm_mma_kernel<1>,
                         cudaFuncAttributeMaxDynamicSharedMemorySize, SMEM_DYN);

    init_counts_kernel<<<1, 32>>>();
    router_kernel<<<T_TOKENS / 8, 256>>>(x, Wr);
    prefix_kernel<<<1, 32>>>();

    conv_split_kernel<<<2048, 256>>>(W1, 1, (NEXP * DDIM * DDIM) / 4);
    conv_split_kernel<<<2048, 256>>>(W2, 2, (NEXP * DDIM * DDIM) / 4);

    dim3 grid(DDIM / BN, MAXTILES);   // (16, 264), compacted tiles
    gemm_mma_kernel<0><<<grid, 256, SMEM_DYN>>>(b1);
    gemm_mma_kernel<1><<<grid, 256, SMEM_DYN>>>(b1);

    combine_kernel<<<(T_TOKENS * DDIM / 4) / 256, 256>>>(b2, out);
}

// round 13
// speedup vs baseline: 1.3449x; 1.3449x over previous
#include <cuda_runtime.h>
#include <cuda_fp16.h>
#include <math.h>
#include <stdint.h>

// Problem constants
#define T_TOKENS 16384
#define DDIM     1024
#define NEXP     8

// GEMM tiling
#define BM 128
#define BN 64
#define BK 64                      // fp16 elems per k-slab = 128B rows
#define LDR 72                     // 64 data + 8 pad = 144B stride (conflict-free)
#define NSLAB (DDIM / BK)          // 16
#define MAXTILES 264

// stage layout (bytes): Ah | Al | Bh
#define A_BYTES (BM * LDR * 2)     // 18432
#define B_BYTES (BN * LDR * 2)     // 9216
#define OFF_AH 0
#define OFF_AL A_BYTES
#define OFF_BH (2 * A_BYTES)
#define STAGE_BYTES (2 * A_BYTES + B_BYTES)        // 46080
#define SMEM_DYN (2 * STAGE_BYTES)                 // 92160 -> 2 CTAs/SM

// ---------------- scratch (static device globals; no allocation) ------------
__device__ int    g_count[NEXP];
__device__ int    g_base[NEXP];
__device__ int    g_tok[NEXP][T_TOKENS];
__device__ int4   g_assign[T_TOKENS];
__device__ float2 g_tw[T_TOKENS];
__device__ int    g_ntiles;
__device__ int    g_te[MAXTILES];
__device__ int    g_trow[MAXTILES];

__device__ __half g_xh[T_TOKENS * DDIM];
__device__ __half g_xl[T_TOKENS * DDIM];
__device__ __half g_w1[NEXP * DDIM * DDIM];
__device__ __half g_w2[NEXP * DDIM * DDIM];
__device__ __half g_Hh[2 * T_TOKENS * DDIM];
__device__ __half g_Hl[2 * T_TOKENS * DDIM];
__device__ float  g_Y[2 * T_TOKENS * DDIM];

// ---------------- helpers ----------------------------------------------------
static __device__ __forceinline__ uint32_t smem_u32(const void* p) {
    uint32_t a;
    asm("{ .reg .u64 t; cvta.to.shared.u64 t, %1; cvt.u32.u64 %0, t; }"
        : "=r"(a) : "l"(p));
    return a;
}
static __device__ __forceinline__ void cp16(uint32_t dst, const void* src) {
    asm volatile("cp.async.cg.shared.global [%0], [%1], 16;" :: "r"(dst), "l"(src));
}
static __device__ __forceinline__ void cp_commit() {
    asm volatile("cp.async.commit_group;" ::: "memory");
}
static __device__ __forceinline__ void cp_wait1() {
    asm volatile("cp.async.wait_group 1;" ::: "memory");
}

static __device__ __forceinline__ void ldsm4(uint32_t* r, const __half* p) {
    uint32_t a = (uint32_t)__cvta_generic_to_shared(p);
    asm volatile("ldmatrix.sync.aligned.m8n8.x4.shared.b16 {%0,%1,%2,%3}, [%4];"
                 : "=r"(r[0]), "=r"(r[1]), "=r"(r[2]), "=r"(r[3])
                 : "r"(a));
}
static __device__ __forceinline__ void mma16816(float* c, const uint32_t* a, const uint32_t* b) {
    asm volatile("mma.sync.aligned.m16n8k16.row.col.f32.f16.f16.f32 "
                 "{%0,%1,%2,%3},{%4,%5,%6,%7},{%8,%9},{%0,%1,%2,%3};"
                 : "+f"(c[0]), "+f"(c[1]), "+f"(c[2]), "+f"(c[3])
                 : "r"(a[0]), "r"(a[1]), "r"(a[2]), "r"(a[3]),
                   "r"(b[0]), "r"(b[1]));
}

// ---------------- init ------------------------------------------------------
__global__ void init_counts_kernel() {
    if (threadIdx.x < NEXP) {
        g_count[threadIdx.x] = 0;
    }
}

// ---------------- fp32 -> fp16 weight conversion ------------------------------
__global__ void conv_half_kernel(const float* __restrict__ src, int which, int n4) {
    __half* dst = (which == 1) ? g_w1 : g_w2;
    int idx = blockIdx.x * blockDim.x + threadIdx.x;
    const int stride = gridDim.x * blockDim.x;
    for (; idx < n4; idx += stride) {
        float4 v = ((const float4*)src)[idx];
        __half2 h01 = __floats2half2_rn(v.x, v.y);
        __half2 h23 = __floats2half2_rn(v.z, v.w);
        uint2 hv;
        hv.x = *reinterpret_cast<uint32_t*>(&h01);
        hv.y = *reinterpret_cast<uint32_t*>(&h23);
        ((uint2*)dst)[idx] = hv;
    }
}

// ---------------- router (also emits x fp16 hi/lo split) ----------------------
__global__ void router_kernel(const float* __restrict__ x,
                              const float* __restrict__ Wr) {
    __shared__ __align__(16) float sWr[NEXP * DDIM];
    for (int i = threadIdx.x; i < NEXP * DDIM; i += blockDim.x) {
        sWr[i] = Wr[i];
    }
    __syncthreads();

    const int warp = threadIdx.x >> 5;
    const int lane = threadIdx.x & 31;
    const int t = blockIdx.x * 8 + warp;

    const float4* xr = (const float4*)(x + (size_t)t * DDIM);
    const float4* wr = (const float4*)sWr;
    uint2* xh = (uint2*)(g_xh + (size_t)t * DDIM);
    uint2* xl = (uint2*)(g_xl + (size_t)t * DDIM);

    float acc[NEXP];
#pragma unroll
    for (int e = 0; e < NEXP; e++) {
        acc[e] = 0.f;
    }

    for (int i = lane; i < DDIM / 4; i += 32) {
        float4 xv = xr[i];
        {
            __half h0 = __float2half_rn(xv.x);
            __half h1 = __float2half_rn(xv.y);
            __half h2 = __float2half_rn(xv.z);
            __half h3 = __float2half_rn(xv.w);
            __half l0 = __float2half_rn(xv.x - __half2float(h0));
            __half l1 = __float2half_rn(xv.y - __half2float(h1));
            __half l2 = __float2half_rn(xv.z - __half2float(h2));
            __half l3 = __float2half_rn(xv.w - __half2float(h3));
            __half2 hp0 = __halves2half2(h0, h1);
            __half2 hp1 = __halves2half2(h2, h3);
            __half2 lp0 = __halves2half2(l0, l1);
            __half2 lp1 = __halves2half2(l2, l3);
            uint2 hv;
            hv.x = *reinterpret_cast<uint32_t*>(&hp0);
            hv.y = *reinterpret_cast<uint32_t*>(&hp1);
            uint2 lv;
            lv.x = *reinterpret_cast<uint32_t*>(&lp0);
            lv.y = *reinterpret_cast<uint32_t*>(&lp1);
            xh[i] = hv;
            xl[i] = lv;
        }
#pragma unroll
        for (int e = 0; e < NEXP; e++) {
            float4 wv = wr[e * (DDIM / 4) + i];
            acc[e] += xv.x * wv.x + xv.y * wv.y + xv.z * wv.z + xv.w * wv.w;
        }
    }
#pragma unroll
    for (int e = 0; e < NEXP; e++) {
#pragma unroll
        for (int off = 16; off; off >>= 1) {
            acc[e] += __shfl_xor_sync(0xffffffffu, acc[e], off);
        }
    }

    if (lane == 0) {
        int i1 = 0;
        float m1 = acc[0];
#pragma unroll
        for (int e = 1; e < NEXP; e++) {
            if (acc[e] > m1) { m1 = acc[e]; i1 = e; }
        }
        int i2 = -1;
        float m2 = -INFINITY;
#pragma unroll
        for (int e = 0; e < NEXP; e++) {
            if (e != i1 && acc[e] > m2) { m2 = acc[e]; i2 = e; }
        }

        float w1 = 1.0f / (1.0f + expf(m2 - m1));
        float w2 = 1.0f - w1;

        int p1 = atomicAdd(&g_count[i1], 1);
        g_tok[i1][p1] = t;
        int p2 = atomicAdd(&g_count[i2], 1);
        g_tok[i2][p2] = t;
        g_assign[t] = make_int4(i1, p1, i2, p2);
        g_tw[t] = make_float2(w1, w2);
    }
}

// ---------------- prefix + tile table -----------------------------------------
__global__ void prefix_kernel() {
    if (threadIdx.x == 0) {
        int s = 0;
        int nt = 0;
#pragma unroll
        for (int e = 0; e < NEXP; e++) {
            g_base[e] = s;
            const int c = g_count[e];
            const int tiles = (c + BM - 1) / BM;
            for (int i = 0; i < tiles; i++) {
                g_te[nt] = e;
                g_trow[nt] = i * BM;
                nt++;
            }
            s += c;
        }
        g_ntiles = nt;
    }
}

// ---------------- gemm building block ------------------------------------------
static __device__ __forceinline__ void compute_slab(
    const __half* sAh, const __half* sAl, const __half* sBh,
    int aLd, int bLd, float acc[2][4][4]) {
#pragma unroll
    for (int kk = 0; kk < BK; kk += 16) {
        uint32_t ah0[4];
        uint32_t ah1[4];
        uint32_t al0[4];
        uint32_t al1[4];
        uint32_t bh0[4];
        uint32_t bh1[4];
        ldsm4(ah0, sAh + aLd + kk);
        ldsm4(ah1, sAh + aLd + 16 * LDR + kk);
        ldsm4(al0, sAl + aLd + kk);
        ldsm4(al1, sAl + aLd + 16 * LDR + kk);
        ldsm4(bh0, sBh + bLd + kk);
        ldsm4(bh1, sBh + bLd + 16 * LDR + kk);

        mma16816(acc[0][0], ah0, &bh0[0]);
        mma16816(acc[0][1], ah0, &bh0[2]);
        mma16816(acc[0][2], ah0, &bh1[0]);
        mma16816(acc[0][3], ah0, &bh1[2]);
        mma16816(acc[1][0], ah1, &bh0[0]);
        mma16816(acc[1][1], ah1, &bh0[2]);
        mma16816(acc[1][2], ah1, &bh1[0]);
        mma16816(acc[1][3], ah1, &bh1[2]);

        mma16816(acc[0][0], al0, &bh0[0]);
        mma16816(acc[0][1], al0, &bh0[2]);
        mma16816(acc[0][2], al0, &bh1[0]);
        mma16816(acc[0][3], al0, &bh1[2]);
        mma16816(acc[1][0], al1, &bh0[0]);
        mma16816(acc[1][1], al1, &bh0[2]);
        mma16816(acc[1][2], al1, &bh1[0]);
        mma16816(acc[1][3], al1, &bh1[2]);
    }
}

// ============================================================================
// fp16x2 tensor-core grouped GEMM (A split hi/lo, B single fp16).
// BK=64 slabs, 2-stage cp.async double buffer, compacted tile grid.
// EPI 0: A = gathered x rows (hi/lo), B = W1[e], gelu(c+b1) -> g_Hh/g_Hl
// EPI 1: A = packed H rows,           B = W2[e], raw c      -> g_Y
// ============================================================================
template <int EPI>
__global__ void __launch_bounds__(256, 2)
gemm_mma_kernel(const float* __restrict__ bias) {
    const int tix = blockIdx.y;
    if (tix >= g_ntiles) { return; }
    const int e    = g_te[tix];
    const int row0 = g_trow[tix];
    const int cnt  = g_count[e];
    const int base = g_base[e];
    const int col0 = blockIdx.x * BN;

    extern __shared__ __align__(128) char dsmem[];
    const uint32_t sb = smem_u32(dsmem);

    const int tid  = threadIdx.x;
    const int lane = tid & 31;
    const int wid  = tid >> 5;

    // ---- cp.async assignment: cq = 16B chunk (0..7), rowq = row (0..31) -------
    const int cq   = tid & 7;
    const int rowq = tid >> 3;

    const __half* Ah;
    const __half* Al;
    const __half* Bh;
    size_t aIdx[4];
    size_t bIdx[2];
    if (EPI == 0) {
        Ah = g_xh;
        Al = g_xl;
        Bh = g_w1;
#pragma unroll
        for (int j = 0; j < 4; j++) {
            int r = row0 + rowq + 32 * j;
            if (r >= cnt) { r = cnt - 1; }
            aIdx[j] = (size_t)g_tok[e][r] * DDIM + cq * 8;
        }
    } else {
        Ah = g_Hh;
        Al = g_Hl;
        Bh = g_w2;
#pragma unroll
        for (int j = 0; j < 4; j++) {
            int r = row0 + rowq + 32 * j;
            if (r >= cnt) { r = cnt - 1; }
            aIdx[j] = (size_t)(base + r) * DDIM + cq * 8;
        }
    }
#pragma unroll
    for (int j = 0; j < 2; j++) {
        bIdx[j] = ((size_t)e * DDIM + col0 + rowq + 32 * j) * DDIM + cq * 8;
    }

    uint32_t oA[4];
#pragma unroll
    for (int j = 0; j < 4; j++) {
        oA[j] = (uint32_t)(rowq + 32 * j) * 144u + (uint32_t)cq * 16u;
    }

    const uint32_t st0 = sb;
    const uint32_t st1 = sb + STAGE_BYTES;
    const __half* s0Ah = (const __half*)(dsmem + OFF_AH);
    const __half* s0Al = (const __half*)(dsmem + OFF_AL);
    const __half* s0Bh = (const __half*)(dsmem + OFF_BH);
    const __half* s1Ah = (const __half*)(dsmem + STAGE_BYTES + OFF_AH);
    const __half* s1Al = (const __half*)(dsmem + STAGE_BYTES + OFF_AL);
    const __half* s1Bh = (const __half*)(dsmem + STAGE_BYTES + OFF_BH);

    // ---- mma fragment smem offsets (fp16 elems) --------------------------------
    const int wm = (wid & 3) * 32;
    const int wn = (wid >> 2) * 32;
    const int aLd = (wm + (lane & 15)) * LDR + ((lane >> 4) << 3);
    const int bLd = (wn + ((lane >> 4) << 3) + (lane & 7)) * LDR + (lane & 8);

    float acc[2][4][4];
#pragma unroll
    for (int i = 0; i < 2; i++) {
#pragma unroll
        for (int j = 0; j < 4; j++) {
#pragma unroll
            for (int q = 0; q < 4; q++) {
                acc[i][j][q] = 0.f;
            }
        }
    }

    auto refill = [&](uint32_t st, int k0) {
#pragma unroll
        for (int j = 0; j < 4; j++) {
            cp16(st + OFF_AH + oA[j], Ah + aIdx[j] + k0);
            cp16(st + OFF_AL + oA[j], Al + aIdx[j] + k0);
        }
#pragma unroll
        for (int j = 0; j < 2; j++) {
            cp16(st + OFF_BH + oA[j], Bh + bIdx[j] + k0);
        }
    };

    // ---- prologue: slabs 0,1 -> stages 0,1 --------------------------------------
    refill(st0, 0);
    cp_commit();
    refill(st1, BK);
    cp_commit();

    // ---- mainloop ----------------------------------------------------------------
    for (int j = 0; j < NSLAB; j += 2) {
        cp_wait1();
        __syncthreads();
        compute_slab(s0Ah, s0Al, s0Bh, aLd, bLd, acc);
        __syncthreads();
        if (j + 2 < NSLAB) {
            refill(st0, (j + 2) * BK);
        }
        cp_commit();

        cp_wait1();
        __syncthreads();
        compute_slab(s1Ah, s1Al, s1Bh, aLd, bLd, acc);
        __syncthreads();
        if (j + 3 < NSLAB) {
            refill(st1, (j + 3) * BK);
        }
        cp_commit();
    }

    // ---- epilogue ----------------------------------------------------------------
    const int r0l = lane >> 2;
    const int c0l = (lane & 3) * 2;
#pragma unroll
    for (int mt = 0; mt < 2; mt++) {
#pragma unroll
        for (int nt = 0; nt < 4; nt++) {
            const int fc = col0 + wn + nt * 8 + c0l;
#pragma unroll
            for (int half = 0; half < 2; half++) {
                const int r = row0 + wm + mt * 16 + r0l + half * 8;
                if (r < cnt) {
                    float v0 = acc[mt][nt][half * 2 + 0];
                    float v1 = acc[mt][nt][half * 2 + 1];
                    if (EPI == 0) {
                        float2 bb = *(const float2*)(bias + (size_t)e * DDIM + fc);
                        v0 += bb.x;
                        v1 += bb.y;
                        v0 = 0.5f * v0 * (1.0f + erff(v0 * 0.70710678118654752f));
                        v1 = 0.5f * v1 * (1.0f + erff(v1 * 0.70710678118654752f));
                        __half h0 = __float2half_rn(v0);
                        __half h1 = __float2half_rn(v1);
                        __half l0 = __float2half_rn(v0 - __half2float(h0));
                        __half l1 = __float2half_rn(v1 - __half2float(h1));
                        *(__half2*)(g_Hh + (size_t)(base + r) * DDIM + fc) =
                            __halves2half2(h0, h1);
                        *(__half2*)(g_Hl + (size_t)(base + r) * DDIM + fc) =
                            __halves2half2(l0, l1);
                    } else {
                        *(float2*)(g_Y + (size_t)(base + r) * DDIM + fc) = make_float2(v0, v1);
                    }
                }
            }
        }
    }
}

// ---------------- combine: out[t] = w1*(y1+b2[e1]) + w2*(y2+b2[e2]) ----------
__global__ void combine_kernel(const float* __restrict__ b2,
                               float* __restrict__ out) {
    const int idx = blockIdx.x * blockDim.x + threadIdx.x;
    const int t = idx >> 8;
    const int c4 = idx & 255;
    int4 a = g_assign[t];
    float2 w = g_tw[t];
    const int s1 = g_base[a.x] + a.y;
    const int s2 = g_base[a.z] + a.w;
    float4 y1 = *(const float4*)(g_Y + (size_t)s1 * DDIM + c4 * 4);
    float4 y2 = *(const float4*)(g_Y + (size_t)s2 * DDIM + c4 * 4);
    float4 v1 = *(const float4*)(b2 + (size_t)a.x * DDIM + c4 * 4);
    float4 v2 = *(const float4*)(b2 + (size_t)a.z * DDIM + c4 * 4);
    float4 o;
    o.x = w.x * (y1.x + v1.x) + w.y * (y2.x + v2.x);
    o.y = w.x * (y1.y + v1.y) + w.y * (y2.y + v2.y);
    o.z = w.x * (y1.z + v1.z) + w.y * (y2.z + v2.z);
    o.w = w.x * (y1.w + v1.w) + w.y * (y2.w + v2.w);
    ((float4*)out)[idx] = o;
}

// ---------------- launch -----------------------------------------------------
extern "C" void kernel_launch(void* const* d_in, const int* in_sizes, int n_in,
                              void* d_out, int out_size) {
    const float* x  = (const float*)d_in[0];
    const float* Wr = (const float*)d_in[1];
    const float* W1 = (const float*)d_in[2];
    const float* b1 = (const float*)d_in[3];
    const float* W2 = (const float*)d_in[4];
    const float* b2 = (const float*)d_in[5];
    float* out = (float*)d_out;

    cudaFuncSetAttribute(gemm_mma_kernel<0>,
                         cudaFuncAttributeMaxDynamicSharedMemorySize, SMEM_DYN);
    cudaFuncSetAttribute(gemm_mma_kernel<1>,
                         cudaFuncAttributeMaxDynamicSharedMemorySize, SMEM_DYN);

    init_counts_kernel<<<1, 32>>>();
    router_kernel<<<T_TOKENS / 8, 256>>>(x, Wr);
    prefix_kernel<<<1, 32>>>();

    conv_half_kernel<<<2048, 256>>>(W1, 1, (NEXP * DDIM * DDIM) / 4);
    conv_half_kernel<<<2048, 256>>>(W2, 2, (NEXP * DDIM * DDIM) / 4);

    dim3 grid(DDIM / BN, MAXTILES);   // (16, 264), compacted tiles
    gemm_mma_kernel<0><<<grid, 256, SMEM_DYN>>>(b1);
    gemm_mma_kernel<1><<<grid, 256, SMEM_DYN>>>(b1);

    combine_kernel<<<(T_TOKENS * DDIM / 4) / 256, 256>>>(b2, out);
}

// round 14
// speedup vs baseline: 1.9454x; 1.4465x over previous
#include <cuda_runtime.h>
#include <cuda_fp16.h>
#include <math.h>
#include <stdint.h>

// Problem constants
#define T_TOKENS 16384
#define DDIM     1024
#define NEXP     8

// GEMM tiling
#define BM 128
#define BN 64
#define BK 64                      // fp16 elems per k-slab = 128B rows
#define LDR 72                     // 64 data + 8 pad = 144B stride (conflict-free)
#define NSLAB (DDIM / BK)          // 16
#define MAXTILES 264

// stage layout (bytes): A | B
#define A_BYTES (BM * LDR * 2)     // 18432
#define B_BYTES (BN * LDR * 2)     // 9216
#define OFF_A 0
#define OFF_B A_BYTES
#define STAGE_BYTES (A_BYTES + B_BYTES)            // 27648
#define SMEM_DYN (2 * STAGE_BYTES)                 // 55296

// ---------------- scratch (static device globals; no allocation) ------------
__device__ int    g_count[NEXP];
__device__ int    g_base[NEXP];
__device__ int    g_tok[NEXP][T_TOKENS];
__device__ int4   g_assign[T_TOKENS];
__device__ float2 g_tw[T_TOKENS];
__device__ int    g_ntiles;
__device__ int    g_te[MAXTILES];
__device__ int    g_trow[MAXTILES];

__device__ __half g_x16[T_TOKENS * DDIM];
__device__ __half g_w1[NEXP * DDIM * DDIM];
__device__ __half g_w2[NEXP * DDIM * DDIM];
__device__ __half g_H[2 * T_TOKENS * DDIM];
__device__ float  g_Y[2 * T_TOKENS * DDIM];

// ---------------- helpers ----------------------------------------------------
static __device__ __forceinline__ uint32_t smem_u32(const void* p) {
    uint32_t a;
    asm("{ .reg .u64 t; cvta.to.shared.u64 t, %1; cvt.u32.u64 %0, t; }"
        : "=r"(a) : "l"(p));
    return a;
}
static __device__ __forceinline__ void cp16(uint32_t dst, const void* src) {
    asm volatile("cp.async.cg.shared.global [%0], [%1], 16;" :: "r"(dst), "l"(src));
}
static __device__ __forceinline__ void cp_commit() {
    asm volatile("cp.async.commit_group;" ::: "memory");
}
static __device__ __forceinline__ void cp_wait1() {
    asm volatile("cp.async.wait_group 1;" ::: "memory");
}

static __device__ __forceinline__ void ldsm4(uint32_t* r, const __half* p) {
    uint32_t a = (uint32_t)__cvta_generic_to_shared(p);
    asm volatile("ldmatrix.sync.aligned.m8n8.x4.shared.b16 {%0,%1,%2,%3}, [%4];"
                 : "=r"(r[0]), "=r"(r[1]), "=r"(r[2]), "=r"(r[3])
                 : "r"(a));
}
static __device__ __forceinline__ void mma16816(float* c, const uint32_t* a, const uint32_t* b) {
    asm volatile("mma.sync.aligned.m16n8k16.row.col.f32.f16.f16.f32 "
                 "{%0,%1,%2,%3},{%4,%5,%6,%7},{%8,%9},{%0,%1,%2,%3};"
                 : "+f"(c[0]), "+f"(c[1]), "+f"(c[2]), "+f"(c[3])
                 : "r"(a[0]), "r"(a[1]), "r"(a[2]), "r"(a[3]),
                   "r"(b[0]), "r"(b[1]));
}

// ---------------- init ------------------------------------------------------
__global__ void init_counts_kernel() {
    if (threadIdx.x < NEXP) {
        g_count[threadIdx.x] = 0;
    }
}

// ---------------- fp32 -> fp16 weight conversion ------------------------------
__global__ void conv_half_kernel(const float* __restrict__ src, int which, int n4) {
    __half* dst = (which == 1) ? g_w1 : g_w2;
    int idx = blockIdx.x * blockDim.x + threadIdx.x;
    const int stride = gridDim.x * blockDim.x;
    for (; idx < n4; idx += stride) {
        float4 v = ((const float4*)src)[idx];
        __half2 h01 = __floats2half2_rn(v.x, v.y);
        __half2 h23 = __floats2half2_rn(v.z, v.w);
        uint2 hv;
        hv.x = *reinterpret_cast<uint32_t*>(&h01);
        hv.y = *reinterpret_cast<uint32_t*>(&h23);
        ((uint2*)dst)[idx] = hv;
    }
}

// ---------------- router (also emits x fp16) ----------------------------------
__global__ void router_kernel(const float* __restrict__ x,
                              const float* __restrict__ Wr) {
    __shared__ __align__(16) float sWr[NEXP * DDIM];
    for (int i = threadIdx.x; i < NEXP * DDIM; i += blockDim.x) {
        sWr[i] = Wr[i];
    }
    __syncthreads();

    const int warp = threadIdx.x >> 5;
    const int lane = threadIdx.x & 31;
    const int t = blockIdx.x * 8 + warp;

    const float4* xr = (const float4*)(x + (size_t)t * DDIM);
    const float4* wr = (const float4*)sWr;
    uint2* xh = (uint2*)(g_x16 + (size_t)t * DDIM);

    float acc[NEXP];
#pragma unroll
    for (int e = 0; e < NEXP; e++) {
        acc[e] = 0.f;
    }

    for (int i = lane; i < DDIM / 4; i += 32) {
        float4 xv = xr[i];
        {
            __half2 h01 = __floats2half2_rn(xv.x, xv.y);
            __half2 h23 = __floats2half2_rn(xv.z, xv.w);
            uint2 hv;
            hv.x = *reinterpret_cast<uint32_t*>(&h01);
            hv.y = *reinterpret_cast<uint32_t*>(&h23);
            xh[i] = hv;
        }
#pragma unroll
        for (int e = 0; e < NEXP; e++) {
            float4 wv = wr[e * (DDIM / 4) + i];
            acc[e] += xv.x * wv.x + xv.y * wv.y + xv.z * wv.z + xv.w * wv.w;
        }
    }
#pragma unroll
    for (int e = 0; e < NEXP; e++) {
#pragma unroll
        for (int off = 16; off; off >>= 1) {
            acc[e] += __shfl_xor_sync(0xffffffffu, acc[e], off);
        }
    }

    if (lane == 0) {
        int i1 = 0;
        float m1 = acc[0];
#pragma unroll
        for (int e = 1; e < NEXP; e++) {
            if (acc[e] > m1) { m1 = acc[e]; i1 = e; }
        }
        int i2 = -1;
        float m2 = -INFINITY;
#pragma unroll
        for (int e = 0; e < NEXP; e++) {
            if (e != i1 && acc[e] > m2) { m2 = acc[e]; i2 = e; }
        }

        float w1 = 1.0f / (1.0f + expf(m2 - m1));
        float w2 = 1.0f - w1;

        int p1 = atomicAdd(&g_count[i1], 1);
        g_tok[i1][p1] = t;
        int p2 = atomicAdd(&g_count[i2], 1);
        g_tok[i2][p2] = t;
        g_assign[t] = make_int4(i1, p1, i2, p2);
        g_tw[t] = make_float2(w1, w2);
    }
}

// ---------------- prefix + tile table -----------------------------------------
__global__ void prefix_kernel() {
    if (threadIdx.x == 0) {
        int s = 0;
        int nt = 0;
#pragma unroll
        for (int e = 0; e < NEXP; e++) {
            g_base[e] = s;
            const int c = g_count[e];
            const int tiles = (c + BM - 1) / BM;
            for (int i = 0; i < tiles; i++) {
                g_te[nt] = e;
                g_trow[nt] = i * BM;
                nt++;
            }
            s += c;
        }
        g_ntiles = nt;
    }
}

// ---------------- gemm building block ------------------------------------------
static __device__ __forceinline__ void compute_slab(
    const __half* sA, const __half* sB,
    int aLd, int bLd, float acc[2][4][4]) {
#pragma unroll
    for (int kk = 0; kk < BK; kk += 16) {
        uint32_t a0[4];
        uint32_t a1[4];
        uint32_t b0[4];
        uint32_t b1[4];
        ldsm4(a0, sA + aLd + kk);
        ldsm4(a1, sA + aLd + 16 * LDR + kk);
        ldsm4(b0, sB + bLd + kk);
        ldsm4(b1, sB + bLd + 16 * LDR + kk);

        mma16816(acc[0][0], a0, &b0[0]);
        mma16816(acc[0][1], a0, &b0[2]);
        mma16816(acc[0][2], a0, &b1[0]);
        mma16816(acc[0][3], a0, &b1[2]);
        mma16816(acc[1][0], a1, &b0[0]);
        mma16816(acc[1][1], a1, &b0[2]);
        mma16816(acc[1][2], a1, &b1[0]);
        mma16816(acc[1][3], a1, &b1[2]);
    }
}

// ============================================================================
// fp16 single-pass tensor-core grouped GEMM.
// BK=64 slabs, 2-stage cp.async double buffer, compacted tile grid.
// EPI 0: A = gathered x rows, B = W1[e], gelu(c+b1) -> g_H (fp16)
// EPI 1: A = packed H rows,   B = W2[e], raw c      -> g_Y (fp32)
// ============================================================================
template <int EPI>
__global__ void __launch_bounds__(256, 2)
gemm_mma_kernel(const float* __restrict__ bias) {
    const int tix = blockIdx.y;
    if (tix >= g_ntiles) { return; }
    const int e    = g_te[tix];
    const int row0 = g_trow[tix];
    const int cnt  = g_count[e];
    const int base = g_base[e];
    const int col0 = blockIdx.x * BN;

    extern __shared__ __align__(128) char dsmem[];
    const uint32_t sb = smem_u32(dsmem);

    const int tid  = threadIdx.x;
    const int lane = tid & 31;
    const int wid  = tid >> 5;

    // ---- cp.async assignment: cq = 16B chunk (0..7), rowq = row (0..31) -------
    const int cq   = tid & 7;
    const int rowq = tid >> 3;

    const __half* Ap;
    const __half* Bp;
    size_t aIdx[4];
    size_t bIdx[2];
    if (EPI == 0) {
        Ap = g_x16;
        Bp = g_w1;
#pragma unroll
        for (int j = 0; j < 4; j++) {
            int r = row0 + rowq + 32 * j;
            if (r >= cnt) { r = cnt - 1; }
            aIdx[j] = (size_t)g_tok[e][r] * DDIM + cq * 8;
        }
    } else {
        Ap = g_H;
        Bp = g_w2;
#pragma unroll
        for (int j = 0; j < 4; j++) {
            int r = row0 + rowq + 32 * j;
            if (r >= cnt) { r = cnt - 1; }
            aIdx[j] = (size_t)(base + r) * DDIM + cq * 8;
        }
    }
#pragma unroll
    for (int j = 0; j < 2; j++) {
        bIdx[j] = ((size_t)e * DDIM + col0 + rowq + 32 * j) * DDIM + cq * 8;
    }

    uint32_t oA[4];
#pragma unroll
    for (int j = 0; j < 4; j++) {
        oA[j] = (uint32_t)(rowq + 32 * j) * 144u + (uint32_t)cq * 16u;
    }

    const uint32_t st0 = sb;
    const uint32_t st1 = sb + STAGE_BYTES;
    const __half* s0A = (const __half*)(dsmem + OFF_A);
    const __half* s0B = (const __half*)(dsmem + OFF_B);
    const __half* s1A = (const __half*)(dsmem + STAGE_BYTES + OFF_A);
    const __half* s1B = (const __half*)(dsmem + STAGE_BYTES + OFF_B);

    // ---- mma fragment smem offsets (fp16 elems) --------------------------------
    const int wm = (wid & 3) * 32;
    const int wn = (wid >> 2) * 32;
    const int aLd = (wm + (lane & 15)) * LDR + ((lane >> 4) << 3);
    const int bLd = (wn + ((lane >> 4) << 3) + (lane & 7)) * LDR + (lane & 8);

    float acc[2][4][4];
#pragma unroll
    for (int i = 0; i < 2; i++) {
#pragma unroll
        for (int j = 0; j < 4; j++) {
#pragma unroll
            for (int q = 0; q < 4; q++) {
                acc[i][j][q] = 0.f;
            }
        }
    }

    auto refill = [&](uint32_t st, int k0) {
#pragma unroll
        for (int j = 0; j < 4; j++) {
            cp16(st + OFF_A + oA[j], Ap + aIdx[j] + k0);
        }
#pragma unroll
        for (int j = 0; j < 2; j++) {
            cp16(st + OFF_B + oA[j], Bp + bIdx[j] + k0);
        }
    };

    // ---- prologue: slabs 0,1 -> stages 0,1 --------------------------------------
    refill(st0, 0);
    cp_commit();
    refill(st1, BK);
    cp_commit();

    // ---- mainloop ----------------------------------------------------------------
    for (int j = 0; j < NSLAB; j += 2) {
        cp_wait1();
        __syncthreads();
        compute_slab(s0A, s0B, aLd, bLd, acc);
        __syncthreads();
        if (j + 2 < NSLAB) {
            refill(st0, (j + 2) * BK);
        }
        cp_commit();

        cp_wait1();
        __syncthreads();
        compute_slab(s1A, s1B, aLd, bLd, acc);
        __syncthreads();
        if (j + 3 < NSLAB) {
            refill(st1, (j + 3) * BK);
        }
        cp_commit();
    }

    // ---- epilogue ----------------------------------------------------------------
    const int r0l = lane >> 2;
    const int c0l = (lane & 3) * 2;
#pragma unroll
    for (int mt = 0; mt < 2; mt++) {
#pragma unroll
        for (int nt = 0; nt < 4; nt++) {
            const int fc = col0 + wn + nt * 8 + c0l;
#pragma unroll
            for (int half = 0; half < 2; half++) {
                const int r = row0 + wm + mt * 16 + r0l + half * 8;
                if (r < cnt) {
                    float v0 = acc[mt][nt][half * 2 + 0];
                    float v1 = acc[mt][nt][half * 2 + 1];
                    if (EPI == 0) {
                        float2 bb = *(const float2*)(bias + (size_t)e * DDIM + fc);
                        v0 += bb.x;
                        v1 += bb.y;
                        v0 = 0.5f * v0 * (1.0f + erff(v0 * 0.70710678118654752f));
                        v1 = 0.5f * v1 * (1.0f + erff(v1 * 0.70710678118654752f));
                        *(__half2*)(g_H + (size_t)(base + r) * DDIM + fc) =
                            __floats2half2_rn(v0, v1);
                    } else {
                        *(float2*)(g_Y + (size_t)(base + r) * DDIM + fc) = make_float2(v0, v1);
                    }
                }
            }
        }
    }
}

// ---------------- combine: out[t] = w1*(y1+b2[e1]) + w2*(y2+b2[e2]) ----------
__global__ void combine_kernel(const float* __restrict__ b2,
                               float* __restrict__ out) {
    const int idx = blockIdx.x * blockDim.x + threadIdx.x;
    const int t = idx >> 8;
    const int c4 = idx & 255;
    int4 a = g_assign[t];
    float2 w = g_tw[t];
    const int s1 = g_base[a.x] + a.y;
    const int s2 = g_base[a.z] + a.w;
    float4 y1 = *(const float4*)(g_Y + (size_t)s1 * DDIM + c4 * 4);
    float4 y2 = *(const float4*)(g_Y + (size_t)s2 * DDIM + c4 * 4);
    float4 v1 = *(const float4*)(b2 + (size_t)a.x * DDIM + c4 * 4);
    float4 v2 = *(const float4*)(b2 + (size_t)a.z * DDIM + c4 * 4);
    float4 o;
    o.x = w.x * (y1.x + v1.x) + w.y * (y2.x + v2.x);
    o.y = w.x * (y1.y + v1.y) + w.y * (y2.y + v2.y);
    o.z = w.x * (y1.z + v1.z) + w.y * (y2.z + v2.z);
    o.w = w.x * (y1.w + v1.w) + w.y * (y2.w + v2.w);
    ((float4*)out)[idx] = o;
}

// ---------------- launch -----------------------------------------------------
extern "C" void kernel_launch(void* const* d_in, const int* in_sizes, int n_in,
                              void* d_out, int out_size) {
    const float* x  = (const float*)d_in[0];
    const float* Wr = (const float*)d_in[1];
    const float* W1 = (const float*)d_in[2];
    const float* b1 = (const float*)d_in[3];
    const float* W2 = (const float*)d_in[4];
    const float* b2 = (const float*)d_in[5];
    float* out = (float*)d_out;

    cudaFuncSetAttribute(gemm_mma_kernel<0>,
                         cudaFuncAttributeMaxDynamicSharedMemorySize, SMEM_DYN);
    cudaFuncSetAttribute(gemm_mma_kernel<1>,
                         cudaFuncAttributeMaxDynamicSharedMemorySize, SMEM_DYN);

    init_counts_kernel<<<1, 32>>>();
    router_kernel<<<T_TOKENS / 8, 256>>>(x, Wr);
    prefix_kernel<<<1, 32>>>();

    conv_half_kernel<<<2048, 256>>>(W1, 1, (NEXP * DDIM * DDIM) / 4);
    conv_half_kernel<<<2048, 256>>>(W2, 2, (NEXP * DDIM * DDIM) / 4);

    dim3 grid(DDIM / BN, MAXTILES);   // (16, 264), compacted tiles
    gemm_mma_kernel<0><<<grid, 256, SMEM_DYN>>>(b1);
    gemm_mma_kernel<1><<<grid, 256, SMEM_DYN>>>(b1);

    combine_kernel<<<(T_TOKENS * DDIM / 4) / 256, 256>>>(b2, out);
}

// round 15
// speedup vs baseline: 2.4432x; 1.2559x over previous
#include <cuda_runtime.h>
#include <cuda_fp16.h>
#include <math.h>
#include <stdint.h>

// Problem constants
#define T_TOKENS 16384
#define DDIM     1024
#define NEXP     8

// GEMM tiling
#define BM 128
#define BN 128
#define BK 64                      // fp16 elems per k-slab = 128B rows
#define LDR 72                     // 64 data + 8 pad = 144B stride (conflict-free)
#define NSLAB (DDIM / BK)          // 16
#define MAXTILES 264

// stage layout (bytes): A | B
#define A_BYTES (BM * LDR * 2)     // 18432
#define B_BYTES (BN * LDR * 2)     // 18432
#define OFF_A 0
#define OFF_B A_BYTES
#define STAGE_BYTES (A_BYTES + B_BYTES)            // 36864
#define SMEM_DYN (2 * STAGE_BYTES)                 // 73728 -> 2 CTAs/SM

// ---------------- scratch (static device globals; no allocation) ------------
__device__ int    g_count[NEXP];
__device__ int    g_base[NEXP];
__device__ int    g_tok[NEXP][T_TOKENS];
__device__ int4   g_assign[T_TOKENS];
__device__ float2 g_tw[T_TOKENS];
__device__ int    g_ntiles;
__device__ int    g_te[MAXTILES];
__device__ int    g_trow[MAXTILES];

__device__ __half g_x16[T_TOKENS * DDIM];
__device__ __half g_w1[NEXP * DDIM * DDIM];
__device__ __half g_w2[NEXP * DDIM * DDIM];
__device__ __half g_H[2 * T_TOKENS * DDIM];
__device__ float  g_Y[2 * T_TOKENS * DDIM];

// ---------------- helpers ----------------------------------------------------
static __device__ __forceinline__ uint32_t smem_u32(const void* p) {
    uint32_t a;
    asm("{ .reg .u64 t; cvta.to.shared.u64 t, %1; cvt.u32.u64 %0, t; }"
        : "=r"(a) : "l"(p));
    return a;
}
static __device__ __forceinline__ void cp16(uint32_t dst, const void* src) {
    asm volatile("cp.async.cg.shared.global [%0], [%1], 16;" :: "r"(dst), "l"(src));
}
static __device__ __forceinline__ void cp_commit() {
    asm volatile("cp.async.commit_group;" ::: "memory");
}
static __device__ __forceinline__ void cp_wait1() {
    asm volatile("cp.async.wait_group 1;" ::: "memory");
}

static __device__ __forceinline__ void ldsm4(uint32_t* r, const __half* p) {
    uint32_t a = (uint32_t)__cvta_generic_to_shared(p);
    asm volatile("ldmatrix.sync.aligned.m8n8.x4.shared.b16 {%0,%1,%2,%3}, [%4];"
                 : "=r"(r[0]), "=r"(r[1]), "=r"(r[2]), "=r"(r[3])
                 : "r"(a));
}
static __device__ __forceinline__ void mma16816(float* c, const uint32_t* a, const uint32_t* b) {
    asm volatile("mma.sync.aligned.m16n8k16.row.col.f32.f16.f16.f32 "
                 "{%0,%1,%2,%3},{%4,%5,%6,%7},{%8,%9},{%0,%1,%2,%3};"
                 : "+f"(c[0]), "+f"(c[1]), "+f"(c[2]), "+f"(c[3])
                 : "r"(a[0]), "r"(a[1]), "r"(a[2]), "r"(a[3]),
                   "r"(b[0]), "r"(b[1]));
}

// ---------------- init ------------------------------------------------------
__global__ void init_counts_kernel() {
    if (threadIdx.x < NEXP) {
        g_count[threadIdx.x] = 0;
    }
}

// ---------------- fp32 -> fp16 weight conversion ------------------------------
__global__ void conv_half_kernel(const float* __restrict__ src, int which, int n4) {
    __half* dst = (which == 1) ? g_w1 : g_w2;
    int idx = blockIdx.x * blockDim.x + threadIdx.x;
    const int stride = gridDim.x * blockDim.x;
    for (; idx < n4; idx += stride) {
        float4 v = ((const float4*)src)[idx];
        __half2 h01 = __floats2half2_rn(v.x, v.y);
        __half2 h23 = __floats2half2_rn(v.z, v.w);
        uint2 hv;
        hv.x = *reinterpret_cast<uint32_t*>(&h01);
        hv.y = *reinterpret_cast<uint32_t*>(&h23);
        ((uint2*)dst)[idx] = hv;
    }
}

// ---------------- router (also emits x fp16) ----------------------------------
__global__ void router_kernel(const float* __restrict__ x,
                              const float* __restrict__ Wr) {
    __shared__ __align__(16) float sWr[NEXP * DDIM];
    for (int i = threadIdx.x; i < NEXP * DDIM; i += blockDim.x) {
        sWr[i] = Wr[i];
    }
    __syncthreads();

    const int warp = threadIdx.x >> 5;
    const int lane = threadIdx.x & 31;
    const int t = blockIdx.x * 8 + warp;

    const float4* xr = (const float4*)(x + (size_t)t * DDIM);
    const float4* wr = (const float4*)sWr;
    uint2* xh = (uint2*)(g_x16 + (size_t)t * DDIM);

    float acc[NEXP];
#pragma unroll
    for (int e = 0; e < NEXP; e++) {
        acc[e] = 0.f;
    }

    for (int i = lane; i < DDIM / 4; i += 32) {
        float4 xv = xr[i];
        {
            __half2 h01 = __floats2half2_rn(xv.x, xv.y);
            __half2 h23 = __floats2half2_rn(xv.z, xv.w);
            uint2 hv;
            hv.x = *reinterpret_cast<uint32_t*>(&h01);
            hv.y = *reinterpret_cast<uint32_t*>(&h23);
            xh[i] = hv;
        }
#pragma unroll
        for (int e = 0; e < NEXP; e++) {
            float4 wv = wr[e * (DDIM / 4) + i];
            acc[e] += xv.x * wv.x + xv.y * wv.y + xv.z * wv.z + xv.w * wv.w;
        }
    }
#pragma unroll
    for (int e = 0; e < NEXP; e++) {
#pragma unroll
        for (int off = 16; off; off >>= 1) {
            acc[e] += __shfl_xor_sync(0xffffffffu, acc[e], off);
        }
    }

    if (lane == 0) {
        int i1 = 0;
        float m1 = acc[0];
#pragma unroll
        for (int e = 1; e < NEXP; e++) {
            if (acc[e] > m1) { m1 = acc[e]; i1 = e; }
        }
        int i2 = -1;
        float m2 = -INFINITY;
#pragma unroll
        for (int e = 0; e < NEXP; e++) {
            if (e != i1 && acc[e] > m2) { m2 = acc[e]; i2 = e; }
        }

        float w1 = 1.0f / (1.0f + expf(m2 - m1));
        float w2 = 1.0f - w1;

        int p1 = atomicAdd(&g_count[i1], 1);
        g_tok[i1][p1] = t;
        int p2 = atomicAdd(&g_count[i2], 1);
        g_tok[i2][p2] = t;
        g_assign[t] = make_int4(i1, p1, i2, p2);
        g_tw[t] = make_float2(w1, w2);
    }
}

// ---------------- prefix + tile table -----------------------------------------
__global__ void prefix_kernel() {
    if (threadIdx.x == 0) {
        int s = 0;
        int nt = 0;
#pragma unroll
        for (int e = 0; e < NEXP; e++) {
            g_base[e] = s;
            const int c = g_count[e];
            const int tiles = (c + BM - 1) / BM;
            for (int i = 0; i < tiles; i++) {
                g_te[nt] = e;
                g_trow[nt] = i * BM;
                nt++;
            }
            s += c;
        }
        g_ntiles = nt;
    }
}

// ---------------- gemm building block ------------------------------------------
static __device__ __forceinline__ void compute_slab(
    const __half* sA, const __half* sB,
    int aLd, int bLd, float acc[2][8][4]) {
#pragma unroll
    for (int kk = 0; kk < BK; kk += 16) {
        uint32_t a0[4];
        uint32_t a1[4];
        uint32_t b0[4];
        uint32_t b1[4];
        uint32_t b2[4];
        uint32_t b3[4];
        ldsm4(a0, sA + aLd + kk);
        ldsm4(a1, sA + aLd + 16 * LDR + kk);
        ldsm4(b0, sB + bLd + kk);
        ldsm4(b1, sB + bLd + 16 * LDR + kk);
        ldsm4(b2, sB + bLd + 32 * LDR + kk);
        ldsm4(b3, sB + bLd + 48 * LDR + kk);

        mma16816(acc[0][0], a0, &b0[0]);
        mma16816(acc[0][1], a0, &b0[2]);
        mma16816(acc[0][2], a0, &b1[0]);
        mma16816(acc[0][3], a0, &b1[2]);
        mma16816(acc[0][4], a0, &b2[0]);
        mma16816(acc[0][5], a0, &b2[2]);
        mma16816(acc[0][6], a0, &b3[0]);
        mma16816(acc[0][7], a0, &b3[2]);
        mma16816(acc[1][0], a1, &b0[0]);
        mma16816(acc[1][1], a1, &b0[2]);
        mma16816(acc[1][2], a1, &b1[0]);
        mma16816(acc[1][3], a1, &b1[2]);
        mma16816(acc[1][4], a1, &b2[0]);
        mma16816(acc[1][5], a1, &b2[2]);
        mma16816(acc[1][6], a1, &b3[0]);
        mma16816(acc[1][7], a1, &b3[2]);
    }
}

// ============================================================================
// fp16 single-pass tensor-core grouped GEMM. 128x128 CTA tile.
// BK=64 slabs, 2-stage cp.async double buffer, compacted tile grid.
// EPI 0: A = gathered x rows, B = W1[e], gelu(c+b1) -> g_H (fp16)
// EPI 1: A = packed H rows,   B = W2[e], raw c      -> g_Y (fp32)
// ============================================================================
template <int EPI>
__global__ void __launch_bounds__(256, 2)
gemm_mma_kernel(const float* __restrict__ bias) {
    const int tix = blockIdx.y;
    if (tix >= g_ntiles) { return; }
    const int e    = g_te[tix];
    const int row0 = g_trow[tix];
    const int cnt  = g_count[e];
    const int base = g_base[e];
    const int col0 = blockIdx.x * BN;

    extern __shared__ __align__(128) char dsmem[];
    const uint32_t sb = smem_u32(dsmem);

    const int tid  = threadIdx.x;
    const int lane = tid & 31;
    const int wid  = tid >> 5;

    // ---- cp.async assignment: cq = 16B chunk (0..7), rowq = row (0..31) -------
    const int cq   = tid & 7;
    const int rowq = tid >> 3;

    const __half* Ap;
    const __half* Bp;
    size_t aIdx[4];
    size_t bIdx[4];
    if (EPI == 0) {
        Ap = g_x16;
        Bp = g_w1;
#pragma unroll
        for (int j = 0; j < 4; j++) {
            int r = row0 + rowq + 32 * j;
            if (r >= cnt) { r = cnt - 1; }
            aIdx[j] = (size_t)g_tok[e][r] * DDIM + cq * 8;
        }
    } else {
        Ap = g_H;
        Bp = g_w2;
#pragma unroll
        for (int j = 0; j < 4; j++) {
            int r = row0 + rowq + 32 * j;
            if (r >= cnt) { r = cnt - 1; }
            aIdx[j] = (size_t)(base + r) * DDIM + cq * 8;
        }
    }
#pragma unroll
    for (int j = 0; j < 4; j++) {
        bIdx[j] = ((size_t)e * DDIM + col0 + rowq + 32 * j) * DDIM + cq * 8;
    }

    uint32_t oA[4];
#pragma unroll
    for (int j = 0; j < 4; j++) {
        oA[j] = (uint32_t)(rowq + 32 * j) * 144u + (uint32_t)cq * 16u;
    }

    const uint32_t st0 = sb;
    const uint32_t st1 = sb + STAGE_BYTES;
    const __half* s0A = (const __half*)(dsmem + OFF_A);
    const __half* s0B = (const __half*)(dsmem + OFF_B);
    const __half* s1A = (const __half*)(dsmem + STAGE_BYTES + OFF_A);
    const __half* s1B = (const __half*)(dsmem + STAGE_BYTES + OFF_B);

    // ---- mma fragment smem offsets: 8 warps = 4 (m) x 2 (n), warp tile 32x64 ---
    const int wm = (wid & 3) * 32;
    const int wn = (wid >> 2) * 64;
    const int aLd = (wm + (lane & 15)) * LDR + ((lane >> 4) << 3);
    const int bLd = (wn + ((lane >> 4) << 3) + (lane & 7)) * LDR + (lane & 8);

    float acc[2][8][4];
#pragma unroll
    for (int i = 0; i < 2; i++) {
#pragma unroll
        for (int j = 0; j < 8; j++) {
#pragma unroll
            for (int q = 0; q < 4; q++) {
                acc[i][j][q] = 0.f;
            }
        }
    }

    auto refill = [&](uint32_t st, int k0) {
#pragma unroll
        for (int j = 0; j < 4; j++) {
            cp16(st + OFF_A + oA[j], Ap + aIdx[j] + k0);
        }
#pragma unroll
        for (int j = 0; j < 4; j++) {
            cp16(st + OFF_B + oA[j], Bp + bIdx[j] + k0);
        }
    };

    // ---- prologue: slabs 0,1 -> stages 0,1 --------------------------------------
    refill(st0, 0);
    cp_commit();
    refill(st1, BK);
    cp_commit();

    // ---- mainloop ----------------------------------------------------------------
    for (int j = 0; j < NSLAB; j += 2) {
        cp_wait1();
        __syncthreads();
        compute_slab(s0A, s0B, aLd, bLd, acc);
        __syncthreads();
        if (j + 2 < NSLAB) {
            refill(st0, (j + 2) * BK);
        }
        cp_commit();

        cp_wait1();
        __syncthreads();
        compute_slab(s1A, s1B, aLd, bLd, acc);
        __syncthreads();
        if (j + 3 < NSLAB) {
            refill(st1, (j + 3) * BK);
        }
        cp_commit();
    }

    // ---- epilogue ----------------------------------------------------------------
    const int r0l = lane >> 2;
    const int c0l = (lane & 3) * 2;
#pragma unroll
    for (int mt = 0; mt < 2; mt++) {
#pragma unroll
        for (int nt = 0; nt < 8; nt++) {
            const int fc = col0 + wn + nt * 8 + c0l;
#pragma unroll
            for (int half = 0; half < 2; half++) {
                const int r = row0 + wm + mt * 16 + r0l + half * 8;
                if (r < cnt) {
                    float v0 = acc[mt][nt][half * 2 + 0];
                    float v1 = acc[mt][nt][half * 2 + 1];
                    if (EPI == 0) {
                        float2 bb = *(const float2*)(bias + (size_t)e * DDIM + fc);
                        v0 += bb.x;
                        v1 += bb.y;
                        v0 = 0.5f * v0 * (1.0f + erff(v0 * 0.70710678118654752f));
                        v1 = 0.5f * v1 * (1.0f + erff(v1 * 0.70710678118654752f));
                        *(__half2*)(g_H + (size_t)(base + r) * DDIM + fc) =
                            __floats2half2_rn(v0, v1);
                    } else {
                        *(float2*)(g_Y + (size_t)(base + r) * DDIM + fc) = make_float2(v0, v1);
                    }
                }
            }
        }
    }
}

// ---------------- combine: out[t] = w1*(y1+b2[e1]) + w2*(y2+b2[e2]) ----------
__global__ void combine_kernel(const float* __restrict__ b2,
                               float* __restrict__ out) {
    const int idx = blockIdx.x * blockDim.x + threadIdx.x;
    const int t = idx >> 8;
    const int c4 = idx & 255;
    int4 a = g_assign[t];
    float2 w = g_tw[t];
    const int s1 = g_base[a.x] + a.y;
    const int s2 = g_base[a.z] + a.w;
    float4 y1 = *(const float4*)(g_Y + (size_t)s1 * DDIM + c4 * 4);
    float4 y2 = *(const float4*)(g_Y + (size_t)s2 * DDIM + c4 * 4);
    float4 v1 = *(const float4*)(b2 + (size_t)a.x * DDIM + c4 * 4);
    float4 v2 = *(const float4*)(b2 + (size_t)a.z * DDIM + c4 * 4);
    float4 o;
    o.x = w.x * (y1.x + v1.x) + w.y * (y2.x + v2.x);
    o.y = w.x * (y1.y + v1.y) + w.y * (y2.y + v2.y);
    o.z = w.x * (y1.z + v1.z) + w.y * (y2.z + v2.z);
    o.w = w.x * (y1.w + v1.w) + w.y * (y2.w + v2.w);
    ((float4*)out)[idx] = o;
}

// ---------------- launch -----------------------------------------------------
extern "C" void kernel_launch(void* const* d_in, const int* in_sizes, int n_in,
                              void* d_out, int out_size) {
    const float* x  = (const float*)d_in[0];
    const float* Wr = (const float*)d_in[1];
    const float* W1 = (const float*)d_in[2];
    const float* b1 = (const float*)d_in[3];
    const float* W2 = (const float*)d_in[4];
    const float* b2 = (const float*)d_in[5];
    float* out = (float*)d_out;

    cudaFuncSetAttribute(gemm_mma_kernel<0>,
                         cudaFuncAttributeMaxDynamicSharedMemorySize, SMEM_DYN);
    cudaFuncSetAttribute(gemm_mma_kernel<1>,
                         cudaFuncAttributeMaxDynamicSharedMemorySize, SMEM_DYN);

    init_counts_kernel<<<1, 32>>>();
    router_kernel<<<T_TOKENS / 8, 256>>>(x, Wr);
    prefix_kernel<<<1, 32>>>();

    conv_half_kernel<<<2048, 256>>>(W1, 1, (NEXP * DDIM * DDIM) / 4);
    conv_half_kernel<<<2048, 256>>>(W2, 2, (NEXP * DDIM * DDIM) / 4);

    dim3 grid(DDIM / BN, MAXTILES);   // (8, 264), compacted tiles
    gemm_mma_kernel<0><<<grid, 256, SMEM_DYN>>>(b1);
    gemm_mma_kernel<1><<<grid, 256, SMEM_DYN>>>(b1);

    combine_kernel<<<(T_TOKENS * DDIM / 4) / 256, 256>>>(b2, out);
}